// round 2
// baseline (speedup 1.0000x reference)
#include <cuda_runtime.h>
#include <cuda_bf16.h>

// Problem constants
#define BATCH 8
#define CH    256
#define NPIX  4096         // 64*64
#define NGRP  8
#define CPG   (CH/NGRP)    // 32
#define EPS   1e-5f

// ---------------- scratch (static device globals; no runtime alloc) -------
__device__ float g_xn  [(size_t)BATCH * CH * NPIX];          //  33.5 MB
__device__ float g_qkv [(size_t)BATCH * 3 * CH * NPIX];      // 100.7 MB
__device__ float g_attn[(size_t)BATCH * NPIX * NPIX];        // 536.9 MB
__device__ float g_aout[(size_t)BATCH * CH * NPIX];          //  33.5 MB

// ---------------- reductions ----------------------------------------------
__device__ __forceinline__ float warpSum(float v) {
    #pragma unroll
    for (int o = 16; o > 0; o >>= 1) v += __shfl_xor_sync(0xffffffffu, v, o);
    return v;
}
__device__ __forceinline__ float warpMax(float v) {
    #pragma unroll
    for (int o = 16; o > 0; o >>= 1) v = fmaxf(v, __shfl_xor_sync(0xffffffffu, v, o));
    return v;
}

// ---------------- GroupNorm: one block per (group, batch) ------------------
__global__ __launch_bounds__(256)
void groupnorm_kernel(const float* __restrict__ x,
                      const float* __restrict__ gamma,
                      const float* __restrict__ beta,
                      float* __restrict__ xn)
{
    const int g = blockIdx.x;
    const int b = blockIdx.y;
    const size_t base = ((size_t)b * CH + (size_t)g * CPG) * NPIX;
    const int cnt4 = CPG * NPIX / 4;   // 32768 float4
    const float4* __restrict__ xp = (const float4*)(x + base);

    float s = 0.f, ss = 0.f;
    for (int i = threadIdx.x; i < cnt4; i += 256) {
        float4 v = xp[i];
        s  += v.x + v.y + v.z + v.w;
        ss += v.x * v.x + v.y * v.y + v.z * v.z + v.w * v.w;
    }
    __shared__ float smS[8], smSS[8], bc[2];
    s  = warpSum(s);
    ss = warpSum(ss);
    int wid = threadIdx.x >> 5, lane = threadIdx.x & 31;
    if (lane == 0) { smS[wid] = s; smSS[wid] = ss; }
    __syncthreads();
    if (wid == 0) {
        float a = (lane < 8) ? smS[lane]  : 0.f;
        float c = (lane < 8) ? smSS[lane] : 0.f;
        a = warpSum(a); c = warpSum(c);
        if (lane == 0) {
            const float invN = 1.f / (float)(CPG * NPIX);
            float mean = a * invN;
            float var  = c * invN - mean * mean;
            bc[0] = mean;
            bc[1] = rsqrtf(var + EPS);
        }
    }
    __syncthreads();
    const float mean = bc[0], inv = bc[1];

    float4* __restrict__ op = (float4*)(xn + base);
    for (int i = threadIdx.x; i < cnt4; i += 256) {
        int c = g * CPG + (i >> (12 - 2));     // (i*4)/NPIX
        float ga = gamma[c] * inv, be = beta[c] - mean * gamma[c] * inv;
        float4 v = xp[i];
        v.x = v.x * ga + be; v.y = v.y * ga + be;
        v.z = v.z * ga + be; v.w = v.w * ga + be;
        op[i] = v;
    }
}

// ---------------- generic tiled fp32 GEMM ----------------------------------
// C[m,n] = alpha * sum_k A*B (+ bias[m]) (+ res[m,n]), per-batch strides.
// TA=false: A is [M,K] row-major.  TA=true: A is [K,M].
// TB=false: B is [K,N] row-major.  TB=true: B is [N,K].
template<bool TA, bool TB, bool HAS_BIAS, bool HAS_RES>
__global__ __launch_bounds__(256)
void gemm_kernel(const float* __restrict__ A, const float* __restrict__ B,
                 float* __restrict__ C,
                 const float* __restrict__ bias, const float* __restrict__ res,
                 int M, int N, int K,
                 long long sA, long long sB, long long sC, long long sRes,
                 float alpha)
{
    constexpr int BM = 64, BN = 64, BK = 32;
    __shared__ float As[BK][BM + 1];
    __shared__ float Bs[BK][BN + 1];

    const int b = blockIdx.z;
    A += (long long)b * sA;
    B += (long long)b * sB;
    C += (long long)b * sC;
    if (HAS_RES) res += (long long)b * sRes;

    const int m0 = blockIdx.y * BM;
    const int n0 = blockIdx.x * BN;
    const int tid = threadIdx.x;
    const int tx = tid & 15;        // n micro-tile
    const int ty = tid >> 4;        // m micro-tile

    float acc[4][4];
    #pragma unroll
    for (int i = 0; i < 4; i++)
        #pragma unroll
        for (int j = 0; j < 4; j++) acc[i][j] = 0.f;

    for (int k0 = 0; k0 < K; k0 += BK) {
        // load A tile -> As[k][m]
        if (TA) {
            #pragma unroll
            for (int r = 0; r < (BK * BM) / 256; r++) {
                int idx = tid + r * 256;
                int k = idx / BM, m = idx % BM;
                As[k][m] = A[(long long)(k0 + k) * M + (m0 + m)];
            }
        } else {
            #pragma unroll
            for (int r = 0; r < (BK * BM) / 256; r++) {
                int idx = tid + r * 256;
                int m = idx / BK, k = idx % BK;
                As[k][m] = A[(long long)(m0 + m) * K + (k0 + k)];
            }
        }
        // load B tile -> Bs[k][n]
        if (TB) {
            #pragma unroll
            for (int r = 0; r < (BK * BN) / 256; r++) {
                int idx = tid + r * 256;
                int n = idx / BK, k = idx % BK;
                Bs[k][n] = B[(long long)(n0 + n) * K + (k0 + k)];
            }
        } else {
            #pragma unroll
            for (int r = 0; r < (BK * BN) / 256; r++) {
                int idx = tid + r * 256;
                int k = idx / BN, n = idx % BN;
                Bs[k][n] = B[(long long)(k0 + k) * N + (n0 + n)];
            }
        }
        __syncthreads();

        #pragma unroll
        for (int kk = 0; kk < BK; kk++) {
            float a[4], bb[4];
            #pragma unroll
            for (int i = 0; i < 4; i++) a[i]  = As[kk][ty * 4 + i];
            #pragma unroll
            for (int j = 0; j < 4; j++) bb[j] = Bs[kk][tx * 4 + j];
            #pragma unroll
            for (int i = 0; i < 4; i++)
                #pragma unroll
                for (int j = 0; j < 4; j++)
                    acc[i][j] = fmaf(a[i], bb[j], acc[i][j]);
        }
        __syncthreads();
    }

    #pragma unroll
    for (int i = 0; i < 4; i++) {
        const int m = m0 + ty * 4 + i;
        const float bv = HAS_BIAS ? bias[m] : 0.f;
        #pragma unroll
        for (int j = 0; j < 4; j++) {
            const int n = n0 + tx * 4 + j;
            float v = alpha * acc[i][j] + bv;
            if (HAS_RES) v += res[(long long)m * N + n];
            C[(long long)m * N + n] = v;
        }
    }
}

// ---------------- row softmax over 4096 columns ----------------------------
__global__ __launch_bounds__(256)
void softmax_kernel(float* __restrict__ attn)
{
    const size_t row = blockIdx.x;
    float4* __restrict__ p = (float4*)(attn + row * (size_t)NPIX);
    const int tid = threadIdx.x;

    float4 v[4];
    float mx = -1e30f;
    #pragma unroll
    for (int i = 0; i < 4; i++) {
        v[i] = p[i * 256 + tid];
        mx = fmaxf(mx, fmaxf(fmaxf(v[i].x, v[i].y), fmaxf(v[i].z, v[i].w)));
    }
    __shared__ float sm[8], bc;
    mx = warpMax(mx);
    int wid = tid >> 5, lane = tid & 31;
    if (lane == 0) sm[wid] = mx;
    __syncthreads();
    if (wid == 0) {
        float a = (lane < 8) ? sm[lane] : -1e30f;
        a = warpMax(a);
        if (lane == 0) bc = a;
    }
    __syncthreads();
    mx = bc;

    float s = 0.f;
    #pragma unroll
    for (int i = 0; i < 4; i++) {
        v[i].x = __expf(v[i].x - mx); v[i].y = __expf(v[i].y - mx);
        v[i].z = __expf(v[i].z - mx); v[i].w = __expf(v[i].w - mx);
        s += v[i].x + v[i].y + v[i].z + v[i].w;
    }
    s = warpSum(s);
    if (lane == 0) sm[wid] = s;
    __syncthreads();
    if (wid == 0) {
        float a = (lane < 8) ? sm[lane] : 0.f;
        a = warpSum(a);
        if (lane == 0) bc = a;
    }
    __syncthreads();
    const float inv = 1.f / bc;

    #pragma unroll
    for (int i = 0; i < 4; i++) {
        v[i].x *= inv; v[i].y *= inv; v[i].z *= inv; v[i].w *= inv;
        p[i * 256 + tid] = v[i];
    }
}

// ---------------- host launcher --------------------------------------------
extern "C" void kernel_launch(void* const* d_in, const int* in_sizes, int n_in,
                              void* d_out, int out_size)
{
    const float* x      = (const float*)d_in[0];
    const float* gn_w   = (const float*)d_in[1];
    const float* gn_b   = (const float*)d_in[2];
    const float* qkv_w  = (const float*)d_in[3];
    const float* qkv_b  = (const float*)d_in[4];
    const float* proj_w = (const float*)d_in[5];
    const float* proj_b = (const float*)d_in[6];
    float* out = (float*)d_out;

    float *xn, *qkv, *attn, *aout;
    cudaGetSymbolAddress((void**)&xn,   g_xn);
    cudaGetSymbolAddress((void**)&qkv,  g_qkv);
    cudaGetSymbolAddress((void**)&attn, g_attn);
    cudaGetSymbolAddress((void**)&aout, g_aout);

    const long long sXN   = (long long)CH * NPIX;          // 256*4096
    const long long sQKV  = (long long)3 * CH * NPIX;      // 768*4096
    const long long sATT  = (long long)NPIX * NPIX;        // 4096*4096
    const float scale = 0.0625f;                            // 1/sqrt(256)

    // 1) GroupNorm
    groupnorm_kernel<<<dim3(NGRP, BATCH), 256>>>(x, gn_w, gn_b, xn);

    // 2) QKV = W[768,256] @ xn[256,4096] + b   (NN, bias)
    gemm_kernel<false, false, true, false><<<dim3(NPIX / 64, (3 * CH) / 64, BATCH), 256>>>(
        qkv_w, xn, qkv, qkv_b, nullptr,
        3 * CH, NPIX, CH, 0, sXN, sQKV, 0, 1.f);

    // 3) scores[n,m] = scale * sum_c q[c,n] k[c,m]   (TN)
    gemm_kernel<true, false, false, false><<<dim3(NPIX / 64, NPIX / 64, BATCH), 256>>>(
        qkv /*q*/, qkv + (long long)CH * NPIX /*k*/, attn, nullptr, nullptr,
        NPIX, NPIX, CH, sQKV, sQKV, sATT, 0, scale);

    // 4) softmax rows
    softmax_kernel<<<BATCH * NPIX, 256>>>(attn);

    // 5) aout[c,n] = sum_m v[c,m] attn[n,m]   (NT)
    gemm_kernel<false, true, false, false><<<dim3(NPIX / 64, CH / 64, BATCH), 256>>>(
        qkv + (long long)2 * CH * NPIX /*v*/, attn, aout, nullptr, nullptr,
        CH, NPIX, NPIX, sQKV, sATT, sXN, 0, 1.f);

    // 6) out = proj_w @ aout + proj_b + x   (NN, bias, residual)
    gemm_kernel<false, false, true, true><<<dim3(NPIX / 64, CH / 64, BATCH), 256>>>(
        proj_w, aout, out, proj_b, x,
        CH, NPIX, CH, 0, sXN, sXN, sXN, 1.f);
}

// round 3
// speedup vs baseline: 1.4980x; 1.4980x over previous
#include <cuda_runtime.h>
#include <cuda_bf16.h>

#define BATCH 8
#define CH    256
#define NPIX  4096
#define NGRP  8
#define CPG   32
#define EPS   1e-5f

typedef __nv_bfloat16  bf16;
typedef __nv_bfloat162 bf162;

// ---------------- scratch (static device globals) --------------------------
__device__ bf16  g_xn_h [(size_t)BATCH * CH * NPIX];
__device__ bf16  g_xn_l [(size_t)BATCH * CH * NPIX];
__device__ bf16  g_qkv_h[(size_t)BATCH * 3 * CH * NPIX];
__device__ bf16  g_qkv_l[(size_t)BATCH * 3 * CH * NPIX];
__device__ float g_attn [(size_t)BATCH * NPIX * NPIX];
__device__ bf16  g_p_h  [(size_t)BATCH * NPIX * NPIX];
__device__ bf16  g_p_l  [(size_t)BATCH * NPIX * NPIX];
__device__ bf16  g_ao_h [(size_t)BATCH * CH * NPIX];
__device__ bf16  g_ao_l [(size_t)BATCH * CH * NPIX];
__device__ bf16  g_w_h  [3 * CH * CH + CH * CH];
__device__ bf16  g_w_l  [3 * CH * CH + CH * CH];

__device__ __forceinline__ void split_bf16(float x, bf16& h, bf16& l) {
    h = __float2bfloat16(x);
    l = __float2bfloat16(x - __bfloat162float(h));
}

__device__ __forceinline__ float warpSum(float v) {
    #pragma unroll
    for (int o = 16; o > 0; o >>= 1) v += __shfl_xor_sync(0xffffffffu, v, o);
    return v;
}
__device__ __forceinline__ float warpMax(float v) {
    #pragma unroll
    for (int o = 16; o > 0; o >>= 1) v = fmaxf(v, __shfl_xor_sync(0xffffffffu, v, o));
    return v;
}

// ---------------- weight split ---------------------------------------------
__global__ __launch_bounds__(256)
void split_weights_kernel(const float* __restrict__ qkv_w,
                          const float* __restrict__ proj_w,
                          bf16* __restrict__ wh, bf16* __restrict__ wl)
{
    int i = blockIdx.x * 256 + threadIdx.x;
    const int nq = 3 * CH * CH;
    float v = (i < nq) ? qkv_w[i] : proj_w[i - nq];
    bf16 h, l;
    split_bf16(v, h, l);
    wh[i] = h; wl[i] = l;
}

// ---------------- GroupNorm -> hi/lo bf16 ----------------------------------
__global__ __launch_bounds__(256)
void groupnorm_kernel(const float* __restrict__ x,
                      const float* __restrict__ gamma,
                      const float* __restrict__ beta,
                      bf16* __restrict__ xnh, bf16* __restrict__ xnl)
{
    const int g = blockIdx.x;
    const int b = blockIdx.y;
    const size_t base = ((size_t)b * CH + (size_t)g * CPG) * NPIX;
    const int cnt4 = CPG * NPIX / 4;
    const float4* __restrict__ xp = (const float4*)(x + base);

    float s = 0.f, ss = 0.f;
    for (int i = threadIdx.x; i < cnt4; i += 256) {
        float4 v = xp[i];
        s  += v.x + v.y + v.z + v.w;
        ss += v.x * v.x + v.y * v.y + v.z * v.z + v.w * v.w;
    }
    __shared__ float smS[8], smSS[8], bc[2];
    s = warpSum(s); ss = warpSum(ss);
    int wid = threadIdx.x >> 5, lane = threadIdx.x & 31;
    if (lane == 0) { smS[wid] = s; smSS[wid] = ss; }
    __syncthreads();
    if (wid == 0) {
        float a = (lane < 8) ? smS[lane]  : 0.f;
        float c = (lane < 8) ? smSS[lane] : 0.f;
        a = warpSum(a); c = warpSum(c);
        if (lane == 0) {
            const float invN = 1.f / (float)(CPG * NPIX);
            float mean = a * invN;
            float var  = c * invN - mean * mean;
            bc[0] = mean; bc[1] = rsqrtf(var + EPS);
        }
    }
    __syncthreads();
    const float mean = bc[0], inv = bc[1];

    bf162* __restrict__ oh = (bf162*)(xnh + base);
    bf162* __restrict__ ol = (bf162*)(xnl + base);
    for (int i = threadIdx.x; i < cnt4; i += 256) {
        int c = g * CPG + (i >> 10);
        float ga = gamma[c] * inv, be = beta[c] - mean * gamma[c] * inv;
        float4 v = xp[i];
        float y0 = v.x * ga + be, y1 = v.y * ga + be;
        float y2 = v.z * ga + be, y3 = v.w * ga + be;
        bf16 h0,l0,h1,l1,h2,l2,h3,l3;
        split_bf16(y0,h0,l0); split_bf16(y1,h1,l1);
        split_bf16(y2,h2,l2); split_bf16(y3,h3,l3);
        oh[2*i]   = __halves2bfloat162(h0,h1);
        oh[2*i+1] = __halves2bfloat162(h2,h3);
        ol[2*i]   = __halves2bfloat162(l0,l1);
        ol[2*i+1] = __halves2bfloat162(l2,l3);
    }
}

// ---------------- MMA helpers ----------------------------------------------
#define LDSM_X4(R, ADDR) \
    asm volatile("ldmatrix.sync.aligned.m8n8.x4.shared.b16 {%0,%1,%2,%3}, [%4];" \
        : "=r"(R[0]), "=r"(R[1]), "=r"(R[2]), "=r"(R[3]) : "r"(ADDR))

#define LDSM_X2T(R, ADDR) \
    asm volatile("ldmatrix.sync.aligned.m8n8.x2.trans.shared.b16 {%0,%1}, [%2];" \
        : "=r"(R[0]), "=r"(R[1]) : "r"(ADDR))

#define MMA_BF16(D, A, B) \
    asm volatile("mma.sync.aligned.m16n8k16.row.col.f32.bf16.bf16.f32 " \
        "{%0,%1,%2,%3}, {%4,%5,%6,%7}, {%8,%9}, {%0,%1,%2,%3};" \
        : "+f"(D[0]), "+f"(D[1]), "+f"(D[2]), "+f"(D[3]) \
        : "r"(A[0]), "r"(A[1]), "r"(A[2]), "r"(A[3]), "r"(B[0]), "r"(B[1]))

// ---------------- bf16x3 split-precision GEMM ------------------------------
// C[M,N] = sum_k A(m,k)*B(k,n), with A = Ah+Al, B = Bh+Bl (lo*lo dropped).
// TA: A stored [K,M] (else [M,K]).  TB: B stored [N,K] (else [K,N]).
// EPI: 0 = Cf = alpha*acc
//      1 = split(acc + bias[m]) -> Ch/Cl
//      2 = split(acc)           -> Ch/Cl
//      3 = Cf = acc + bias[m] + res[m,n]
template<bool TA, bool TB, int EPI>
__global__ __launch_bounds__(256)
void gemm_bf16x3(const bf16* __restrict__ Ah, const bf16* __restrict__ Al,
                 const bf16* __restrict__ Bh, const bf16* __restrict__ Bl,
                 float* __restrict__ Cf, bf16* __restrict__ Ch, bf16* __restrict__ Cl,
                 const float* __restrict__ bias, const float* __restrict__ res,
                 int M, int N, int K,
                 long long sA, long long sB, long long sC, long long sRes,
                 float alpha)
{
    constexpr int BM = 128, BN = 64, BK = 32;
    __shared__ __align__(16) bf16 As_h[BM][BK + 8];
    __shared__ __align__(16) bf16 As_l[BM][BK + 8];
    __shared__ __align__(16) bf16 Bs_h[BK][BN + 8];
    __shared__ __align__(16) bf16 Bs_l[BK][BN + 8];

    const int bz = blockIdx.z;
    Ah += (long long)bz * sA;  Al += (long long)bz * sA;
    Bh += (long long)bz * sB;  Bl += (long long)bz * sB;

    const int m0 = blockIdx.y * BM;
    const int n0 = blockIdx.x * BN;
    const int tid  = threadIdx.x;
    const int lane = tid & 31;
    const int warp = tid >> 5;
    const int wm = warp >> 1;   // 0..3
    const int wn = warp & 1;    // 0..1

    float acc[2][4][4];
    #pragma unroll
    for (int i = 0; i < 2; i++)
        #pragma unroll
        for (int j = 0; j < 4; j++)
            #pragma unroll
            for (int e = 0; e < 4; e++) acc[i][j][e] = 0.f;

    for (int k0 = 0; k0 < K; k0 += BK) {
        // ---- load A tile -> As[m][k]
        if (!TA) {
            #pragma unroll
            for (int v = tid; v < BM * (BK / 8); v += 256) {
                int m = v >> 2, kv = (v & 3) << 3;
                long long ga = (long long)(m0 + m) * K + k0 + kv;
                *(uint4*)&As_h[m][kv] = *(const uint4*)&Ah[ga];
                *(uint4*)&As_l[m][kv] = *(const uint4*)&Al[ga];
            }
        } else {
            #pragma unroll
            for (int v = tid; v < BK * (BM / 8); v += 256) {
                int k = v >> 4, mv = (v & 15) << 3;
                long long ga = (long long)(k0 + k) * M + m0 + mv;
                uint4 dh = *(const uint4*)&Ah[ga];
                uint4 dl = *(const uint4*)&Al[ga];
                bf16 th[8]; *(uint4*)th = dh;
                bf16 tl[8]; *(uint4*)tl = dl;
                #pragma unroll
                for (int e = 0; e < 8; e++) {
                    As_h[mv + e][k] = th[e];
                    As_l[mv + e][k] = tl[e];
                }
            }
        }
        // ---- load B tile -> Bs[k][n]
        if (!TB) {
            #pragma unroll
            for (int v = tid; v < BK * (BN / 8); v += 256) {
                int k = v >> 3, nv = (v & 7) << 3;
                long long gb = (long long)(k0 + k) * N + n0 + nv;
                *(uint4*)&Bs_h[k][nv] = *(const uint4*)&Bh[gb];
                *(uint4*)&Bs_l[k][nv] = *(const uint4*)&Bl[gb];
            }
        } else {
            #pragma unroll
            for (int v = tid; v < BN * (BK / 8); v += 256) {
                int n = v >> 2, kv = (v & 3) << 3;
                long long gb = (long long)(n0 + n) * K + k0 + kv;
                uint4 dh = *(const uint4*)&Bh[gb];
                uint4 dl = *(const uint4*)&Bl[gb];
                bf16 th[8]; *(uint4*)th = dh;
                bf16 tl[8]; *(uint4*)tl = dl;
                #pragma unroll
                for (int e = 0; e < 8; e++) {
                    Bs_h[kv + e][n] = th[e];
                    Bs_l[kv + e][n] = tl[e];
                }
            }
        }
        __syncthreads();

        #pragma unroll
        for (int kk = 0; kk < BK; kk += 16) {
            unsigned ah[2][4], al[2][4], bh[4][2], bl[4][2];
            #pragma unroll
            for (int i = 0; i < 2; i++) {
                unsigned addr_h = (unsigned)__cvta_generic_to_shared(
                    &As_h[wm * 32 + i * 16 + (lane & 15)][kk + (lane >> 4) * 8]);
                LDSM_X4(ah[i], addr_h);
                unsigned addr_l = (unsigned)__cvta_generic_to_shared(
                    &As_l[wm * 32 + i * 16 + (lane & 15)][kk + (lane >> 4) * 8]);
                LDSM_X4(al[i], addr_l);
            }
            #pragma unroll
            for (int j = 0; j < 4; j++) {
                unsigned addr_h = (unsigned)__cvta_generic_to_shared(
                    &Bs_h[kk + (lane & 15)][wn * 32 + j * 8]);
                LDSM_X2T(bh[j], addr_h);
                unsigned addr_l = (unsigned)__cvta_generic_to_shared(
                    &Bs_l[kk + (lane & 15)][wn * 32 + j * 8]);
                LDSM_X2T(bl[j], addr_l);
            }
            #pragma unroll
            for (int i = 0; i < 2; i++)
                #pragma unroll
                for (int j = 0; j < 4; j++) {
                    MMA_BF16(acc[i][j], ah[i], bh[j]);
                    MMA_BF16(acc[i][j], al[i], bh[j]);
                    MMA_BF16(acc[i][j], ah[i], bl[j]);
                }
        }
        __syncthreads();
    }

    // ---- epilogue
    float* CfB = (EPI == 0 || EPI == 3) ? Cf + (long long)bz * sC : nullptr;
    bf16*  ChB = (EPI == 1 || EPI == 2) ? Ch + (long long)bz * sC : nullptr;
    bf16*  ClB = (EPI == 1 || EPI == 2) ? Cl + (long long)bz * sC : nullptr;
    const float* resB = (EPI == 3) ? res + (long long)bz * sRes : nullptr;

    #pragma unroll
    for (int i = 0; i < 2; i++)
        #pragma unroll
        for (int j = 0; j < 4; j++) {
            int r0 = m0 + wm * 32 + i * 16 + (lane >> 2);
            int c  = n0 + wn * 32 + j * 8 + ((lane & 3) << 1);
            #pragma unroll
            for (int h = 0; h < 2; h++) {
                int r = r0 + h * 8;
                float x0 = acc[i][j][2 * h], x1 = acc[i][j][2 * h + 1];
                long long off = (long long)r * N + c;
                if (EPI == 0) {
                    *(float2*)&CfB[off] = make_float2(alpha * x0, alpha * x1);
                } else if (EPI == 1 || EPI == 2) {
                    float v0 = x0, v1 = x1;
                    if (EPI == 1) { float bv = bias[r]; v0 += bv; v1 += bv; }
                    bf16 h0,l0,h1,l1;
                    split_bf16(v0, h0, l0); split_bf16(v1, h1, l1);
                    *(bf162*)&ChB[off] = __halves2bfloat162(h0, h1);
                    *(bf162*)&ClB[off] = __halves2bfloat162(l0, l1);
                } else { // EPI == 3
                    float bv = bias[r];
                    float v0 = x0 + bv + resB[off];
                    float v1 = x1 + bv + resB[off + 1];
                    *(float2*)&CfB[off] = make_float2(v0, v1);
                }
            }
        }
}

// ---------------- softmax: fp32 in -> hi/lo bf16 out ------------------------
__global__ __launch_bounds__(256)
void softmax_kernel(const float* __restrict__ attn,
                    bf16* __restrict__ ph, bf16* __restrict__ pl)
{
    const size_t row = blockIdx.x;
    const float4* __restrict__ p = (const float4*)(attn + row * (size_t)NPIX);
    const int tid = threadIdx.x;

    float4 v[4];
    float mx = -1e30f;
    #pragma unroll
    for (int i = 0; i < 4; i++) {
        v[i] = p[i * 256 + tid];
        mx = fmaxf(mx, fmaxf(fmaxf(v[i].x, v[i].y), fmaxf(v[i].z, v[i].w)));
    }
    __shared__ float sm[8], bc;
    mx = warpMax(mx);
    int wid = tid >> 5, lane = tid & 31;
    if (lane == 0) sm[wid] = mx;
    __syncthreads();
    if (wid == 0) {
        float a = (lane < 8) ? sm[lane] : -1e30f;
        a = warpMax(a);
        if (lane == 0) bc = a;
    }
    __syncthreads();
    mx = bc;

    float s = 0.f;
    #pragma unroll
    for (int i = 0; i < 4; i++) {
        v[i].x = __expf(v[i].x - mx); v[i].y = __expf(v[i].y - mx);
        v[i].z = __expf(v[i].z - mx); v[i].w = __expf(v[i].w - mx);
        s += v[i].x + v[i].y + v[i].z + v[i].w;
    }
    s = warpSum(s);
    if (lane == 0) sm[wid] = s;
    __syncthreads();
    if (wid == 0) {
        float a = (lane < 8) ? sm[lane] : 0.f;
        a = warpSum(a);
        if (lane == 0) bc = a;
    }
    __syncthreads();
    const float inv = 1.f / bc;

    bf162* __restrict__ oh = (bf162*)(ph + row * (size_t)NPIX);
    bf162* __restrict__ ol = (bf162*)(pl + row * (size_t)NPIX);
    #pragma unroll
    for (int i = 0; i < 4; i++) {
        float y0 = v[i].x * inv, y1 = v[i].y * inv;
        float y2 = v[i].z * inv, y3 = v[i].w * inv;
        bf16 h0,l0,h1,l1,h2,l2,h3,l3;
        split_bf16(y0,h0,l0); split_bf16(y1,h1,l1);
        split_bf16(y2,h2,l2); split_bf16(y3,h3,l3);
        int idx = i * 256 + tid;
        oh[2*idx]   = __halves2bfloat162(h0,h1);
        oh[2*idx+1] = __halves2bfloat162(h2,h3);
        ol[2*idx]   = __halves2bfloat162(l0,l1);
        ol[2*idx+1] = __halves2bfloat162(l2,l3);
    }
}

// ---------------- host launcher --------------------------------------------
extern "C" void kernel_launch(void* const* d_in, const int* in_sizes, int n_in,
                              void* d_out, int out_size)
{
    const float* x      = (const float*)d_in[0];
    const float* gn_w   = (const float*)d_in[1];
    const float* gn_b   = (const float*)d_in[2];
    const float* qkv_w  = (const float*)d_in[3];
    const float* qkv_b  = (const float*)d_in[4];
    const float* proj_w = (const float*)d_in[5];
    const float* proj_b = (const float*)d_in[6];
    float* out = (float*)d_out;

    bf16 *xnh, *xnl, *qkvh, *qkvl, *ph, *pl, *aoh, *aol, *wh, *wl;
    float* attn;
    cudaGetSymbolAddress((void**)&xnh,  g_xn_h);
    cudaGetSymbolAddress((void**)&xnl,  g_xn_l);
    cudaGetSymbolAddress((void**)&qkvh, g_qkv_h);
    cudaGetSymbolAddress((void**)&qkvl, g_qkv_l);
    cudaGetSymbolAddress((void**)&attn, g_attn);
    cudaGetSymbolAddress((void**)&ph,   g_p_h);
    cudaGetSymbolAddress((void**)&pl,   g_p_l);
    cudaGetSymbolAddress((void**)&aoh,  g_ao_h);
    cudaGetSymbolAddress((void**)&aol,  g_ao_l);
    cudaGetSymbolAddress((void**)&wh,   g_w_h);
    cudaGetSymbolAddress((void**)&wl,   g_w_l);

    const long long sXN  = (long long)CH * NPIX;
    const long long sQKV = (long long)3 * CH * NPIX;
    const long long sATT = (long long)NPIX * NPIX;
    const float scale = 0.0625f;

    // 0) split weights to hi/lo
    split_weights_kernel<<<(3 * CH * CH + CH * CH) / 256, 256>>>(qkv_w, proj_w, wh, wl);

    // 1) GroupNorm -> xn hi/lo
    groupnorm_kernel<<<dim3(NGRP, BATCH), 256>>>(x, gn_w, gn_b, xnh, xnl);

    // 2) QKV[768,4096] = W[768,256] @ xn[256,4096] + bias -> hi/lo
    gemm_bf16x3<false, false, 1><<<dim3(NPIX / 64, (3 * CH) / 128, BATCH), 256>>>(
        wh, wl, xnh, xnl, nullptr, qkvh, qkvl, qkv_b, nullptr,
        3 * CH, NPIX, CH, 0, sXN, sQKV, 0, 1.f);

    // 3) scores[4096,4096] = scale * q^T k   (A = q [K=256,M], B = k [K=256,N])
    gemm_bf16x3<true, false, 0><<<dim3(NPIX / 64, NPIX / 128, BATCH), 256>>>(
        qkvh, qkvl, qkvh + (long long)CH * NPIX, qkvl + (long long)CH * NPIX,
        attn, nullptr, nullptr, nullptr, nullptr,
        NPIX, NPIX, CH, sQKV, sQKV, sATT, 0, scale);

    // 4) softmax rows -> P hi/lo
    softmax_kernel<<<BATCH * NPIX, 256>>>(attn, ph, pl);

    // 5) aout[256,4096] = v[256,4096(m)] @ P^T   (B = P [N,K] transposed)
    gemm_bf16x3<false, true, 2><<<dim3(NPIX / 64, CH / 128, BATCH), 256>>>(
        qkvh + (long long)2 * CH * NPIX, qkvl + (long long)2 * CH * NPIX,
        ph, pl, nullptr, aoh, aol, nullptr, nullptr,
        CH, NPIX, NPIX, sQKV, sATT, sXN, 0, 1.f);

    // 6) out = proj_w @ aout + proj_b + x
    gemm_bf16x3<false, false, 3><<<dim3(NPIX / 64, CH / 128, BATCH), 256>>>(
        wh + 3 * CH * CH, wl + 3 * CH * CH, aoh, aol,
        out, nullptr, nullptr, proj_b, x,
        CH, NPIX, CH, 0, sXN, sXN, sXN, 1.f);
}

// round 4
// speedup vs baseline: 3.4808x; 2.3237x over previous
#include <cuda_runtime.h>
#include <cuda_bf16.h>

#define BATCH 8
#define CH    256
#define NPIX  4096
#define NGRP  8
#define CPG   32
#define EPS   1e-5f

typedef __nv_bfloat16  bf16;
typedef __nv_bfloat162 bf162;

// ---------------- scratch (static device globals) --------------------------
__device__ bf16  g_xn_h [(size_t)BATCH * CH * NPIX];
__device__ bf16  g_xn_l [(size_t)BATCH * CH * NPIX];
__device__ bf16  g_qkv_h[(size_t)BATCH * 3 * CH * NPIX];
__device__ bf16  g_qkv_l[(size_t)BATCH * 3 * CH * NPIX];
__device__ float g_attn [(size_t)BATCH * NPIX * NPIX];
__device__ bf16  g_p_h  [(size_t)BATCH * NPIX * NPIX];
__device__ bf16  g_p_l  [(size_t)BATCH * NPIX * NPIX];
__device__ bf16  g_ao_h [(size_t)BATCH * CH * NPIX];
__device__ bf16  g_ao_l [(size_t)BATCH * CH * NPIX];
__device__ bf16  g_w_h  [3 * CH * CH + CH * CH];
__device__ bf16  g_w_l  [3 * CH * CH + CH * CH];

__device__ __forceinline__ void split_bf16(float x, bf16& h, bf16& l) {
    h = __float2bfloat16(x);
    l = __float2bfloat16(x - __bfloat162float(h));
}
__device__ __forceinline__ float warpSum(float v) {
    #pragma unroll
    for (int o = 16; o > 0; o >>= 1) v += __shfl_xor_sync(0xffffffffu, v, o);
    return v;
}
__device__ __forceinline__ float warpMax(float v) {
    #pragma unroll
    for (int o = 16; o > 0; o >>= 1) v = fmaxf(v, __shfl_xor_sync(0xffffffffu, v, o));
    return v;
}

// ---------------- weight split ---------------------------------------------
__global__ __launch_bounds__(256)
void split_weights_kernel(const float* __restrict__ qkv_w,
                          const float* __restrict__ proj_w,
                          bf16* __restrict__ wh, bf16* __restrict__ wl)
{
    int i = blockIdx.x * 256 + threadIdx.x;
    const int nq = 3 * CH * CH;
    float v = (i < nq) ? qkv_w[i] : proj_w[i - nq];
    bf16 h, l;
    split_bf16(v, h, l);
    wh[i] = h; wl[i] = l;
}

// ---------------- GroupNorm -> hi/lo bf16 ----------------------------------
__global__ __launch_bounds__(256)
void groupnorm_kernel(const float* __restrict__ x,
                      const float* __restrict__ gamma,
                      const float* __restrict__ beta,
                      bf16* __restrict__ xnh, bf16* __restrict__ xnl)
{
    const int g = blockIdx.x;
    const int b = blockIdx.y;
    const size_t base = ((size_t)b * CH + (size_t)g * CPG) * NPIX;
    const int cnt4 = CPG * NPIX / 4;
    const float4* __restrict__ xp = (const float4*)(x + base);

    float s = 0.f, ss = 0.f;
    for (int i = threadIdx.x; i < cnt4; i += 256) {
        float4 v = xp[i];
        s  += v.x + v.y + v.z + v.w;
        ss += v.x * v.x + v.y * v.y + v.z * v.z + v.w * v.w;
    }
    __shared__ float smS[8], smSS[8], bc[2];
    s = warpSum(s); ss = warpSum(ss);
    int wid = threadIdx.x >> 5, lane = threadIdx.x & 31;
    if (lane == 0) { smS[wid] = s; smSS[wid] = ss; }
    __syncthreads();
    if (wid == 0) {
        float a = (lane < 8) ? smS[lane]  : 0.f;
        float c = (lane < 8) ? smSS[lane] : 0.f;
        a = warpSum(a); c = warpSum(c);
        if (lane == 0) {
            const float invN = 1.f / (float)(CPG * NPIX);
            float mean = a * invN;
            float var  = c * invN - mean * mean;
            bc[0] = mean; bc[1] = rsqrtf(var + EPS);
        }
    }
    __syncthreads();
    const float mean = bc[0], inv = bc[1];

    bf162* __restrict__ oh = (bf162*)(xnh + base);
    bf162* __restrict__ ol = (bf162*)(xnl + base);
    for (int i = threadIdx.x; i < cnt4; i += 256) {
        int c = g * CPG + (i >> 10);
        float ga = gamma[c] * inv, be = beta[c] - mean * gamma[c] * inv;
        float4 v = xp[i];
        float y0 = v.x * ga + be, y1 = v.y * ga + be;
        float y2 = v.z * ga + be, y3 = v.w * ga + be;
        bf16 h0,l0,h1,l1,h2,l2,h3,l3;
        split_bf16(y0,h0,l0); split_bf16(y1,h1,l1);
        split_bf16(y2,h2,l2); split_bf16(y3,h3,l3);
        oh[2*i]   = __halves2bfloat162(h0,h1);
        oh[2*i+1] = __halves2bfloat162(h2,h3);
        ol[2*i]   = __halves2bfloat162(l0,l1);
        ol[2*i+1] = __halves2bfloat162(l2,l3);
    }
}

// ---------------- MMA / async helpers --------------------------------------
#define LDSM_X4(R, ADDR) \
    asm volatile("ldmatrix.sync.aligned.m8n8.x4.shared.b16 {%0,%1,%2,%3}, [%4];" \
        : "=r"(R[0]), "=r"(R[1]), "=r"(R[2]), "=r"(R[3]) : "r"(ADDR))
#define LDSM_X4T(R, ADDR) \
    asm volatile("ldmatrix.sync.aligned.m8n8.x4.trans.shared.b16 {%0,%1,%2,%3}, [%4];" \
        : "=r"(R[0]), "=r"(R[1]), "=r"(R[2]), "=r"(R[3]) : "r"(ADDR))
#define LDSM_X2T(R, ADDR) \
    asm volatile("ldmatrix.sync.aligned.m8n8.x2.trans.shared.b16 {%0,%1}, [%2];" \
        : "=r"(R[0]), "=r"(R[1]) : "r"(ADDR))
#define LDSM_X2(R, ADDR) \
    asm volatile("ldmatrix.sync.aligned.m8n8.x2.shared.b16 {%0,%1}, [%2];" \
        : "=r"(R[0]), "=r"(R[1]) : "r"(ADDR))
#define MMA_BF16(D, A, B) \
    asm volatile("mma.sync.aligned.m16n8k16.row.col.f32.bf16.bf16.f32 " \
        "{%0,%1,%2,%3}, {%4,%5,%6,%7}, {%8,%9}, {%0,%1,%2,%3};" \
        : "+f"(D[0]), "+f"(D[1]), "+f"(D[2]), "+f"(D[3]) \
        : "r"(A[0]), "r"(A[1]), "r"(A[2]), "r"(A[3]), "r"(B[0]), "r"(B[1]))

__device__ __forceinline__ void cpa16(bf16* dst, const bf16* src) {
    unsigned d = (unsigned)__cvta_generic_to_shared(dst);
    asm volatile("cp.async.cg.shared.global [%0], [%1], 16;" :: "r"(d), "l"(src));
}
#define CP_COMMIT() asm volatile("cp.async.commit_group;")
#define CP_WAIT(N)  asm volatile("cp.async.wait_group %0;" :: "n"(N))

// ---------------- bf16x3 split-precision GEMM, cp.async double-buffered ----
// C = sum_k A*B with A=Ah+Al, B=Bh+Bl (lo*lo dropped). Tiles stored in their
// natural layout; transpose handled by ldmatrix variant selection.
// TA: A stored [K,M]. TB: B stored [N,K].
// EPI: 0 Cf=alpha*acc | 1 split(acc+bias)->Ch/Cl | 2 split(acc)->Ch/Cl
//      3 Cf=acc+bias+res
template<bool TA, bool TB, int EPI>
__global__ __launch_bounds__(256)
void gemm_bf16x3(const bf16* __restrict__ Ah, const bf16* __restrict__ Al,
                 const bf16* __restrict__ Bh, const bf16* __restrict__ Bl,
                 float* __restrict__ Cf, bf16* __restrict__ Ch, bf16* __restrict__ Cl,
                 const float* __restrict__ bias, const float* __restrict__ res,
                 int M, int N, int K,
                 long long sA, long long sB, long long sC, long long sRes,
                 float alpha)
{
    constexpr int BM = 128, BN = 64, BK = 32;
    constexpr int SA    = TA ? (BM + 8) : (BK + 8);      // A row stride
    constexpr int A_ELE = TA ? BK * (BM + 8) : BM * (BK + 8);
    constexpr int SBs   = TB ? (BK + 8) : (BN + 8);      // B row stride
    constexpr int B_ELE = TB ? BN * (BK + 8) : BK * (BN + 8);
    constexpr int STAGE = 2 * A_ELE + 2 * B_ELE;

    extern __shared__ __align__(16) bf16 smem[];

    const int bz = blockIdx.z;
    Ah += (long long)bz * sA;  Al += (long long)bz * sA;
    Bh += (long long)bz * sB;  Bl += (long long)bz * sB;

    const int m0 = blockIdx.y * BM;
    const int n0 = blockIdx.x * BN;
    const int tid  = threadIdx.x;
    const int lane = tid & 31;
    const int warp = tid >> 5;
    const int wm = warp >> 1;
    const int wn = warp & 1;

    float acc[2][4][4];
    #pragma unroll
    for (int i = 0; i < 2; i++)
        #pragma unroll
        for (int j = 0; j < 4; j++)
            #pragma unroll
            for (int e = 0; e < 4; e++) acc[i][j][e] = 0.f;

    // tile loader (cp.async, fully vectorized, natural layout)
    auto load_tiles = [&](int s, int k0) {
        bf16* aH = smem + s * STAGE;
        bf16* aL = aH + A_ELE;
        bf16* bH = aL + A_ELE;
        bf16* bL = bH + B_ELE;
        if (!TA) {
            #pragma unroll
            for (int v = tid; v < BM * (BK / 8); v += 256) {
                int m = v >> 2, kv = (v & 3) << 3;
                long long g = (long long)(m0 + m) * K + k0 + kv;
                cpa16(aH + m * SA + kv, Ah + g);
                cpa16(aL + m * SA + kv, Al + g);
            }
        } else {
            #pragma unroll
            for (int v = tid; v < BK * (BM / 8); v += 256) {
                int k = v >> 4, mv = (v & 15) << 3;
                long long g = (long long)(k0 + k) * M + m0 + mv;
                cpa16(aH + k * SA + mv, Ah + g);
                cpa16(aL + k * SA + mv, Al + g);
            }
        }
        if (!TB) {
            #pragma unroll
            for (int v = tid; v < BK * (BN / 8); v += 256) {
                int k = v >> 3, nv = (v & 7) << 3;
                long long g = (long long)(k0 + k) * N + n0 + nv;
                cpa16(bH + k * SBs + nv, Bh + g);
                cpa16(bL + k * SBs + nv, Bl + g);
            }
        } else {
            #pragma unroll
            for (int v = tid; v < BN * (BK / 8); v += 256) {
                int n = v >> 2, kv = (v & 3) << 3;
                long long g = (long long)(n0 + n) * K + k0 + kv;
                cpa16(bH + n * SBs + kv, Bh + g);
                cpa16(bL + n * SBs + kv, Bl + g);
            }
        }
    };

    const int nIter = K / BK;
    load_tiles(0, 0);
    CP_COMMIT();

    for (int it = 0; it < nIter; it++) {
        const int cur = it & 1;
        if (it + 1 < nIter) {
            load_tiles(cur ^ 1, (it + 1) * BK);
            CP_COMMIT();
            CP_WAIT(1);
        } else {
            CP_WAIT(0);
        }
        __syncthreads();

        bf16* aH = smem + cur * STAGE;
        bf16* aL = aH + A_ELE;
        bf16* bH = aL + A_ELE;
        bf16* bL = bH + B_ELE;

        #pragma unroll
        for (int kk = 0; kk < BK; kk += 16) {
            unsigned ah[2][4], al[2][4], bh[4][2], bl[4][2];
            #pragma unroll
            for (int i = 0; i < 2; i++) {
                const int mb = wm * 32 + i * 16;
                if (!TA) {
                    unsigned ad = (unsigned)__cvta_generic_to_shared(
                        aH + (mb + (lane & 15)) * SA + kk + ((lane >> 4) << 3));
                    LDSM_X4(ah[i], ad);
                    ad = (unsigned)__cvta_generic_to_shared(
                        aL + (mb + (lane & 15)) * SA + kk + ((lane >> 4) << 3));
                    LDSM_X4(al[i], ad);
                } else {
                    unsigned ad = (unsigned)__cvta_generic_to_shared(
                        aH + (kk + (lane & 7) + ((lane & 16) >> 1)) * SA + mb + (lane & 8));
                    LDSM_X4T(ah[i], ad);
                    ad = (unsigned)__cvta_generic_to_shared(
                        aL + (kk + (lane & 7) + ((lane & 16) >> 1)) * SA + mb + (lane & 8));
                    LDSM_X4T(al[i], ad);
                }
            }
            #pragma unroll
            for (int j = 0; j < 4; j++) {
                const int nb = wn * 32 + j * 8;
                if (!TB) {
                    unsigned ad = (unsigned)__cvta_generic_to_shared(
                        bH + (kk + (lane & 15)) * SBs + nb);
                    LDSM_X2T(bh[j], ad);
                    ad = (unsigned)__cvta_generic_to_shared(
                        bL + (kk + (lane & 15)) * SBs + nb);
                    LDSM_X2T(bl[j], ad);
                } else {
                    unsigned ad = (unsigned)__cvta_generic_to_shared(
                        bH + (nb + (lane & 7)) * SBs + kk + (lane & 8));
                    LDSM_X2(bh[j], ad);
                    ad = (unsigned)__cvta_generic_to_shared(
                        bL + (nb + (lane & 7)) * SBs + kk + (lane & 8));
                    LDSM_X2(bl[j], ad);
                }
            }
            #pragma unroll
            for (int i = 0; i < 2; i++)
                #pragma unroll
                for (int j = 0; j < 4; j++) {
                    MMA_BF16(acc[i][j], ah[i], bh[j]);
                    MMA_BF16(acc[i][j], al[i], bh[j]);
                    MMA_BF16(acc[i][j], ah[i], bl[j]);
                }
        }
        __syncthreads();
    }

    // ---- epilogue
    float* CfB = (EPI == 0 || EPI == 3) ? Cf + (long long)bz * sC : nullptr;
    bf16*  ChB = (EPI == 1 || EPI == 2) ? Ch + (long long)bz * sC : nullptr;
    bf16*  ClB = (EPI == 1 || EPI == 2) ? Cl + (long long)bz * sC : nullptr;
    const float* resB = (EPI == 3) ? res + (long long)bz * sRes : nullptr;

    #pragma unroll
    for (int i = 0; i < 2; i++)
        #pragma unroll
        for (int j = 0; j < 4; j++) {
            int r0 = m0 + wm * 32 + i * 16 + (lane >> 2);
            int c  = n0 + wn * 32 + j * 8 + ((lane & 3) << 1);
            #pragma unroll
            for (int h = 0; h < 2; h++) {
                int r = r0 + h * 8;
                float x0 = acc[i][j][2 * h], x1 = acc[i][j][2 * h + 1];
                long long off = (long long)r * N + c;
                if (EPI == 0) {
                    *(float2*)&CfB[off] = make_float2(alpha * x0, alpha * x1);
                } else if (EPI == 1 || EPI == 2) {
                    float v0 = x0, v1 = x1;
                    if (EPI == 1) { float bv = bias[r]; v0 += bv; v1 += bv; }
                    bf16 h0,l0,h1,l1;
                    split_bf16(v0, h0, l0); split_bf16(v1, h1, l1);
                    *(bf162*)&ChB[off] = __halves2bfloat162(h0, h1);
                    *(bf162*)&ClB[off] = __halves2bfloat162(l0, l1);
                } else {
                    float bv = bias[r];
                    float v0 = x0 + bv + resB[off];
                    float v1 = x1 + bv + resB[off + 1];
                    *(float2*)&CfB[off] = make_float2(v0, v1);
                }
            }
        }
}

// ---------------- softmax: fp32 in -> hi/lo bf16 out ------------------------
__global__ __launch_bounds__(256)
void softmax_kernel(const float* __restrict__ attn,
                    bf16* __restrict__ ph, bf16* __restrict__ pl)
{
    const size_t row = blockIdx.x;
    const float4* __restrict__ p = (const float4*)(attn + row * (size_t)NPIX);
    const int tid = threadIdx.x;

    float4 v[4];
    float mx = -1e30f;
    #pragma unroll
    for (int i = 0; i < 4; i++) {
        v[i] = p[i * 256 + tid];
        mx = fmaxf(mx, fmaxf(fmaxf(v[i].x, v[i].y), fmaxf(v[i].z, v[i].w)));
    }
    __shared__ float sm[8], bc;
    mx = warpMax(mx);
    int wid = tid >> 5, lane = tid & 31;
    if (lane == 0) sm[wid] = mx;
    __syncthreads();
    if (wid == 0) {
        float a = (lane < 8) ? sm[lane] : -1e30f;
        a = warpMax(a);
        if (lane == 0) bc = a;
    }
    __syncthreads();
    mx = bc;

    float s = 0.f;
    #pragma unroll
    for (int i = 0; i < 4; i++) {
        v[i].x = __expf(v[i].x - mx); v[i].y = __expf(v[i].y - mx);
        v[i].z = __expf(v[i].z - mx); v[i].w = __expf(v[i].w - mx);
        s += v[i].x + v[i].y + v[i].z + v[i].w;
    }
    s = warpSum(s);
    if (lane == 0) sm[wid] = s;
    __syncthreads();
    if (wid == 0) {
        float a = (lane < 8) ? sm[lane] : 0.f;
        a = warpSum(a);
        if (lane == 0) bc = a;
    }
    __syncthreads();
    const float inv = 1.f / bc;

    bf162* __restrict__ oh = (bf162*)(ph + row * (size_t)NPIX);
    bf162* __restrict__ ol = (bf162*)(pl + row * (size_t)NPIX);
    #pragma unroll
    for (int i = 0; i < 4; i++) {
        float y0 = v[i].x * inv, y1 = v[i].y * inv;
        float y2 = v[i].z * inv, y3 = v[i].w * inv;
        bf16 h0,l0,h1,l1,h2,l2,h3,l3;
        split_bf16(y0,h0,l0); split_bf16(y1,h1,l1);
        split_bf16(y2,h2,l2); split_bf16(y3,h3,l3);
        int idx = i * 256 + tid;
        oh[2*idx]   = __halves2bfloat162(h0,h1);
        oh[2*idx+1] = __halves2bfloat162(h2,h3);
        ol[2*idx]   = __halves2bfloat162(l0,l1);
        ol[2*idx+1] = __halves2bfloat162(l2,l3);
    }
}

// ---------------- host launcher --------------------------------------------
extern "C" void kernel_launch(void* const* d_in, const int* in_sizes, int n_in,
                              void* d_out, int out_size)
{
    const float* x      = (const float*)d_in[0];
    const float* gn_w   = (const float*)d_in[1];
    const float* gn_b   = (const float*)d_in[2];
    const float* qkv_w  = (const float*)d_in[3];
    const float* qkv_b  = (const float*)d_in[4];
    const float* proj_w = (const float*)d_in[5];
    const float* proj_b = (const float*)d_in[6];
    float* out = (float*)d_out;

    bf16 *xnh, *xnl, *qkvh, *qkvl, *ph, *pl, *aoh, *aol, *wh, *wl;
    float* attn;
    cudaGetSymbolAddress((void**)&xnh,  g_xn_h);
    cudaGetSymbolAddress((void**)&xnl,  g_xn_l);
    cudaGetSymbolAddress((void**)&qkvh, g_qkv_h);
    cudaGetSymbolAddress((void**)&qkvl, g_qkv_l);
    cudaGetSymbolAddress((void**)&attn, g_attn);
    cudaGetSymbolAddress((void**)&ph,   g_p_h);
    cudaGetSymbolAddress((void**)&pl,   g_p_l);
    cudaGetSymbolAddress((void**)&aoh,  g_ao_h);
    cudaGetSymbolAddress((void**)&aol,  g_ao_l);
    cudaGetSymbolAddress((void**)&wh,   g_w_h);
    cudaGetSymbolAddress((void**)&wl,   g_w_l);

    const long long sXN  = (long long)CH * NPIX;
    const long long sQKV = (long long)3 * CH * NPIX;
    const long long sATT = (long long)NPIX * NPIX;
    const float scale = 0.0625f;

    // dynamic smem sizes (2 stages x (2*A_ELE + 2*B_ELE) bf16)
    const int smemFF = 2 * (2 * 128 * 40 + 2 * 32 * 72) * 2;   // 59392
    const int smemTF = 2 * (2 * 32 * 136 + 2 * 32 * 72) * 2;   // 53248
    const int smemFT = 2 * (2 * 128 * 40 + 2 * 64 * 40) * 2;   // 61440

    cudaFuncSetAttribute(gemm_bf16x3<false, false, 1>,
                         cudaFuncAttributeMaxDynamicSharedMemorySize, smemFF);
    cudaFuncSetAttribute(gemm_bf16x3<true, false, 0>,
                         cudaFuncAttributeMaxDynamicSharedMemorySize, smemTF);
    cudaFuncSetAttribute(gemm_bf16x3<false, true, 2>,
                         cudaFuncAttributeMaxDynamicSharedMemorySize, smemFT);
    cudaFuncSetAttribute(gemm_bf16x3<false, false, 3>,
                         cudaFuncAttributeMaxDynamicSharedMemorySize, smemFF);

    // 0) split weights to hi/lo
    split_weights_kernel<<<(3 * CH * CH + CH * CH) / 256, 256>>>(qkv_w, proj_w, wh, wl);

    // 1) GroupNorm -> xn hi/lo
    groupnorm_kernel<<<dim3(NGRP, BATCH), 256>>>(x, gn_w, gn_b, xnh, xnl);

    // 2) QKV[768,4096] = W[768,256] @ xn[256,4096] + bias -> hi/lo
    gemm_bf16x3<false, false, 1><<<dim3(NPIX / 64, (3 * CH) / 128, BATCH), 256, smemFF>>>(
        wh, wl, xnh, xnl, nullptr, qkvh, qkvl, qkv_b, nullptr,
        3 * CH, NPIX, CH, 0, sXN, sQKV, 0, 1.f);

    // 3) scores = scale * q^T k   (A = q stored [K=256, M=4096])
    gemm_bf16x3<true, false, 0><<<dim3(NPIX / 64, NPIX / 128, BATCH), 256, smemTF>>>(
        qkvh, qkvl, qkvh + (long long)CH * NPIX, qkvl + (long long)CH * NPIX,
        attn, nullptr, nullptr, nullptr, nullptr,
        NPIX, NPIX, CH, sQKV, sQKV, sATT, 0, scale);

    // 4) softmax rows -> P hi/lo
    softmax_kernel<<<BATCH * NPIX, 256>>>(attn, ph, pl);

    // 5) aout[256,4096] = v @ P^T   (B = P stored [N=4096, K=4096])
    gemm_bf16x3<false, true, 2><<<dim3(NPIX / 64, CH / 128, BATCH), 256, smemFT>>>(
        qkvh + (long long)2 * CH * NPIX, qkvl + (long long)2 * CH * NPIX,
        ph, pl, nullptr, aoh, aol, nullptr, nullptr,
        CH, NPIX, NPIX, sQKV, sATT, sXN, 0, 1.f);

    // 6) out = proj_w @ aout + proj_b + x
    gemm_bf16x3<false, false, 3><<<dim3(NPIX / 64, CH / 128, BATCH), 256, smemFF>>>(
        wh + 3 * CH * CH, wl + 3 * CH * CH, aoh, aol,
        out, nullptr, nullptr, proj_b, x,
        CH, NPIX, CH, 0, sXN, sXN, sXN, 1.f);
}